// round 2
// baseline (speedup 1.0000x reference)
#include <cuda_runtime.h>
#include <cuda_bf16.h>
#include <float.h>

// Scratch for per-row argmax results (allocation-free rule: __device__ global).
__device__ int g_argmax[4096];

// ---------------------------------------------------------------------------
// Kernel 1: per-row argmax over vocab. One CTA per row, 256 threads.
// 4x float4 batched loads per iteration for high MLP. First-index tie-break
// matches jnp.argmax semantics.
// ---------------------------------------------------------------------------
__global__ __launch_bounds__(256, 8)
void argmax_rows_kernel(const float* __restrict__ logits, int vocab) {
    const int row = blockIdx.x;
    const float* rowp = logits + (size_t)row * (size_t)vocab;

    float best = -FLT_MAX;
    int bidx = 0x7FFFFFFF;

    const int nv4 = vocab >> 2;
    const float4* __restrict__ p4 = reinterpret_cast<const float4*>(rowp);
    const int step = blockDim.x;

    // Main loop: 4 independent float4 loads issued back-to-back (MLP=4+).
    int i = threadIdx.x;
    for (; i + 3 * step < nv4; i += 4 * step) {
        float4 a = p4[i];
        float4 b = p4[i + step];
        float4 c = p4[i + 2 * step];
        float4 d = p4[i + 3 * step];
        int ia = i << 2, ib = (i + step) << 2, ic = (i + 2 * step) << 2, id = (i + 3 * step) << 2;
        // Per-thread visited indices strictly increase within each group and
        // across groups, so strict '>' preserves earliest-index ties.
        if (a.x > best) { best = a.x; bidx = ia; }
        if (a.y > best) { best = a.y; bidx = ia + 1; }
        if (a.z > best) { best = a.z; bidx = ia + 2; }
        if (a.w > best) { best = a.w; bidx = ia + 3; }
        if (b.x > best) { best = b.x; bidx = ib; }
        if (b.y > best) { best = b.y; bidx = ib + 1; }
        if (b.z > best) { best = b.z; bidx = ib + 2; }
        if (b.w > best) { best = b.w; bidx = ib + 3; }
        if (c.x > best) { best = c.x; bidx = ic; }
        if (c.y > best) { best = c.y; bidx = ic + 1; }
        if (c.z > best) { best = c.z; bidx = ic + 2; }
        if (c.w > best) { best = c.w; bidx = ic + 3; }
        if (d.x > best) { best = d.x; bidx = id; }
        if (d.y > best) { best = d.y; bidx = id + 1; }
        if (d.z > best) { best = d.z; bidx = id + 2; }
        if (d.w > best) { best = d.w; bidx = id + 3; }
    }
    for (; i < nv4; i += step) {
        float4 v = p4[i];
        int base = i << 2;
        if (v.x > best) { best = v.x; bidx = base; }
        if (v.y > best) { best = v.y; bidx = base + 1; }
        if (v.z > best) { best = v.z; bidx = base + 2; }
        if (v.w > best) { best = v.w; bidx = base + 3; }
    }
    // Scalar tail (vocab % 4). Tail indices exceed all vector indices.
    for (int t = (nv4 << 2) + threadIdx.x; t < vocab; t += step) {
        float v = rowp[t];
        if (v > best) { best = v; bidx = t; }
    }

    // Warp reduction with (value desc, index asc) ordering.
    #pragma unroll
    for (int off = 16; off > 0; off >>= 1) {
        float ov = __shfl_down_sync(0xFFFFFFFFu, best, off);
        int   oi = __shfl_down_sync(0xFFFFFFFFu, bidx, off);
        if (ov > best || (ov == best && oi < bidx)) { best = ov; bidx = oi; }
    }

    __shared__ float svals[8];
    __shared__ int   sidx[8];
    const int wid = threadIdx.x >> 5;
    const int lid = threadIdx.x & 31;
    if (lid == 0) { svals[wid] = best; sidx[wid] = bidx; }
    __syncthreads();

    if (wid == 0) {
        const int nwarps = (blockDim.x + 31) >> 5;
        best = (lid < nwarps) ? svals[lid] : -FLT_MAX;
        bidx = (lid < nwarps) ? sidx[lid]  : 0x7FFFFFFF;
        #pragma unroll
        for (int off = 4; off > 0; off >>= 1) {
            float ov = __shfl_down_sync(0xFFFFFFFFu, best, off);
            int   oi = __shfl_down_sync(0xFFFFFFFFu, bidx, off);
            if (ov > best || (ov == best && oi < bidx)) { best = ov; bidx = oi; }
        }
        if (lid == 0) g_argmax[row] = bidx;
    }
}

// ---------------------------------------------------------------------------
// Kernel 2: speculative-accept epilogue. One thread per batch row.
// spec_token_ids may arrive as int32, int64, or float32 depending on harness
// dtype coercion; detect on-device. Token values are < 2^17, so:
//   - int words are < 0x20000
//   - float32 bit patterns (token >= 1) are >= 0x3F800000
//   - int64 storage has every odd 32-bit word == 0
// Output is written as FLOAT32 (-1.0f for rejected), matching the harness's
// coerced output dtype.
// ---------------------------------------------------------------------------
__global__ void accept_kernel(const unsigned int* __restrict__ spec_words,
                              float* __restrict__ out, int B, int k) {
    // --- dtype detection (uniform across threads; words sit in L2) ---
    int big = 0;                 // words that look like float bit patterns
    int odd_nonzero = 0;
    #pragma unroll
    for (int w = 0; w < 32; w++) {
        unsigned int x = spec_words[w];
        if (x >= 0x01000000u) big++;
        if ((w & 1) && x != 0u) odd_nonzero++;
    }
    int mode;                    // 0 = int32, 1 = int64, 2 = float32
    if (big > 0)             mode = 2;
    else if (odd_nonzero == 0) mode = 1;
    else                     mode = 0;

    const int b = blockIdx.x * blockDim.x + threadIdx.x;
    if (b >= B) return;

    const int kp1 = k + 1;
    int n_acc = 0;
    bool acc = true;
    for (int j = 0; j < k; j++) {
        long long s;
        if (mode == 2) {
            float f = reinterpret_cast<const float*>(spec_words)[(size_t)b * k + j];
            s = (long long)f;    // tokens < 2^24: exact in float32
        } else if (mode == 1) {
            s = reinterpret_cast<const long long*>(spec_words)[(size_t)b * k + j];
        } else {
            s = (long long)reinterpret_cast<const int*>(spec_words)[(size_t)b * k + j];
        }
        int o = g_argmax[b * kp1 + j];
        if (acc && (long long)o == s) n_acc++; else acc = false;
    }
    for (int j = 0; j < kp1; j++) {
        out[b * kp1 + j] = (j <= n_acc) ? (float)g_argmax[b * kp1 + j] : -1.0f;
    }
}

extern "C" void kernel_launch(void* const* d_in, const int* in_sizes, int n_in,
                              void* d_out, int out_size) {
    const float* logits = (const float*)d_in[0];
    const unsigned int* spec = (const unsigned int*)d_in[1];

    // Geometry: rows = out_size = B*(k+1); in_sizes[1] = B*k  =>  B = rows - B*k
    const int rows  = out_size;
    const int nspec = in_sizes[1];
    const int B     = rows - nspec;
    const int k     = nspec / B;
    const int vocab = (int)((long long)in_sizes[0] / rows);

    argmax_rows_kernel<<<rows, 256>>>(logits, vocab);
    accept_kernel<<<(B + 127) / 128, 128>>>(spec, (float*)d_out, B, k);
}

// round 3
// speedup vs baseline: 1.0004x; 1.0004x over previous
#include <cuda_runtime.h>
#include <cuda_bf16.h>
#include <float.h>

// Scratch (allocation-free rule: __device__ globals).
__device__ int g_argmax[4096];
__device__ unsigned int g_done = 0;   // threadfence-reduction counter; reset by last CTA

// ---------------------------------------------------------------------------
// Fused kernel: per-row argmax over vocab (one CTA per row, 256 threads),
// plus a last-CTA-done epilogue that performs the speculative-accept logic.
// ---------------------------------------------------------------------------
__global__ __launch_bounds__(256, 8)
void rejection_sampler_kernel(const float* __restrict__ logits,
                              const unsigned int* __restrict__ spec_words,
                              float* __restrict__ out,
                              int vocab, int rows, int B, int k) {
    const int row = blockIdx.x;
    const float* rowp = logits + (size_t)row * (size_t)vocab;

    float best = -FLT_MAX;
    int bidx = 0x7FFFFFFF;

    const int nv4 = vocab >> 2;
    const float4* __restrict__ p4 = reinterpret_cast<const float4*>(rowp);
    const int step = blockDim.x;

    // Main loop: 4 independent streaming float4 loads per iteration (MLP>=4).
    int i = threadIdx.x;
    for (; i + 3 * step < nv4; i += 4 * step) {
        float4 a = __ldcs(&p4[i]);
        float4 b = __ldcs(&p4[i + step]);
        float4 c = __ldcs(&p4[i + 2 * step]);
        float4 d = __ldcs(&p4[i + 3 * step]);
        int ia = i << 2, ib = (i + step) << 2, ic = (i + 2 * step) << 2, id = (i + 3 * step) << 2;
        // Per-thread visited indices strictly increase, so strict '>' keeps
        // the earliest index on ties (jnp.argmax semantics).
        if (a.x > best) { best = a.x; bidx = ia; }
        if (a.y > best) { best = a.y; bidx = ia + 1; }
        if (a.z > best) { best = a.z; bidx = ia + 2; }
        if (a.w > best) { best = a.w; bidx = ia + 3; }
        if (b.x > best) { best = b.x; bidx = ib; }
        if (b.y > best) { best = b.y; bidx = ib + 1; }
        if (b.z > best) { best = b.z; bidx = ib + 2; }
        if (b.w > best) { best = b.w; bidx = ib + 3; }
        if (c.x > best) { best = c.x; bidx = ic; }
        if (c.y > best) { best = c.y; bidx = ic + 1; }
        if (c.z > best) { best = c.z; bidx = ic + 2; }
        if (c.w > best) { best = c.w; bidx = ic + 3; }
        if (d.x > best) { best = d.x; bidx = id; }
        if (d.y > best) { best = d.y; bidx = id + 1; }
        if (d.z > best) { best = d.z; bidx = id + 2; }
        if (d.w > best) { best = d.w; bidx = id + 3; }
    }
    for (; i < nv4; i += step) {
        float4 v = __ldcs(&p4[i]);
        int base = i << 2;
        if (v.x > best) { best = v.x; bidx = base; }
        if (v.y > best) { best = v.y; bidx = base + 1; }
        if (v.z > best) { best = v.z; bidx = base + 2; }
        if (v.w > best) { best = v.w; bidx = base + 3; }
    }
    for (int t = (nv4 << 2) + threadIdx.x; t < vocab; t += step) {
        float v = rowp[t];
        if (v > best) { best = v; bidx = t; }
    }

    // Warp reduction with (value desc, index asc) ordering.
    #pragma unroll
    for (int off = 16; off > 0; off >>= 1) {
        float ov = __shfl_down_sync(0xFFFFFFFFu, best, off);
        int   oi = __shfl_down_sync(0xFFFFFFFFu, bidx, off);
        if (ov > best || (ov == best && oi < bidx)) { best = ov; bidx = oi; }
    }

    __shared__ float svals[8];
    __shared__ int   sidx[8];
    __shared__ bool  s_last;
    const int wid = threadIdx.x >> 5;
    const int lid = threadIdx.x & 31;
    if (lid == 0) { svals[wid] = best; sidx[wid] = bidx; }
    __syncthreads();

    if (wid == 0) {
        const int nwarps = (blockDim.x + 31) >> 5;
        best = (lid < nwarps) ? svals[lid] : -FLT_MAX;
        bidx = (lid < nwarps) ? sidx[lid]  : 0x7FFFFFFF;
        #pragma unroll
        for (int off = 4; off > 0; off >>= 1) {
            float ov = __shfl_down_sync(0xFFFFFFFFu, best, off);
            int   oi = __shfl_down_sync(0xFFFFFFFFu, bidx, off);
            if (ov > best || (ov == best && oi < bidx)) { best = ov; bidx = oi; }
        }
        if (lid == 0) {
            g_argmax[row] = bidx;
            // Publish result, then count this CTA as done.
            __threadfence();
            unsigned int prev = atomicAdd(&g_done, 1u);
            s_last = (prev == (unsigned int)(rows - 1));
        }
    }
    __syncthreads();

    // ---------- Epilogue: only the last-finishing CTA runs this ----------
    if (!s_last) return;

    const int b = threadIdx.x;
    if (b < B) {
        // spec dtype detection: tokens < 2^17, so int words < 0x20000;
        // float32 patterns (>=1.0) are >= 0x3F800000; int64 -> odd words zero.
        int big = 0, odd_nonzero = 0;
        #pragma unroll
        for (int w = 0; w < 32; w++) {
            unsigned int x = spec_words[w];
            if (x >= 0x01000000u) big++;
            if ((w & 1) && x != 0u) odd_nonzero++;
        }
        int mode = (big > 0) ? 2 : (odd_nonzero == 0 ? 1 : 0); // 2=f32,1=i64,0=i32

        const int kp1 = k + 1;
        int n_acc = 0;
        bool acc = true;
        for (int j = 0; j < k; j++) {
            long long s;
            if (mode == 2) {
                float f = reinterpret_cast<const float*>(spec_words)[(size_t)b * k + j];
                s = (long long)f;
            } else if (mode == 1) {
                s = reinterpret_cast<const long long*>(spec_words)[(size_t)b * k + j];
            } else {
                s = (long long)reinterpret_cast<const int*>(spec_words)[(size_t)b * k + j];
            }
            int o = g_argmax[b * kp1 + j];
            if (acc && (long long)o == s) n_acc++; else acc = false;
        }
        for (int j = 0; j < kp1; j++) {
            out[b * kp1 + j] = (j <= n_acc) ? (float)g_argmax[b * kp1 + j] : -1.0f;
        }
    }
    __syncthreads();
    // Reset counter for the next (graph-replayed) invocation. Only the last
    // CTA reaches here, so this is race-free and deterministic.
    if (threadIdx.x == 0) g_done = 0;
}

extern "C" void kernel_launch(void* const* d_in, const int* in_sizes, int n_in,
                              void* d_out, int out_size) {
    const float* logits = (const float*)d_in[0];
    const unsigned int* spec = (const unsigned int*)d_in[1];

    const int rows  = out_size;          // B*(k+1)
    const int nspec = in_sizes[1];       // B*k
    const int B     = rows - nspec;
    const int k     = nspec / B;
    const int vocab = (int)((long long)in_sizes[0] / rows);

    rejection_sampler_kernel<<<rows, 256>>>(logits, spec, (float*)d_out,
                                            vocab, rows, B, k);
}

// round 4
// speedup vs baseline: 1.0060x; 1.0057x over previous
#include <cuda_runtime.h>
#include <cuda_bf16.h>
#include <float.h>

// Scratch (allocation-free rule: __device__ globals; zero-initialized at load,
// and the epilogue CTA restores zeros for graph replay determinism).
__device__ unsigned long long g_key[4096];   // per-row packed (ordered_val, ~idx)
__device__ int g_argmax[4096];
__device__ unsigned int g_done = 0;

// Ordered-float encoding: monotonic uint mapping for non-NaN floats.
__device__ __forceinline__ unsigned int float_ou(float x) {
    unsigned int u = __float_as_uint(x);
    return (u & 0x80000000u) ? ~u : (u | 0x80000000u);
}
__device__ __forceinline__ float ou_float(unsigned int ou) {
    unsigned int u = (ou & 0x80000000u) ? (ou ^ 0x80000000u) : ~ou;
    return __uint_as_float(u);
}

// ---------------------------------------------------------------------------
// Balanced fused kernel: every CTA processes an equal contiguous chunk of the
// flattened logits (in float4 units). Chunks span at most 2 row boundaries;
// each row-portion is block-reduced and merged into g_key[row] via atomicMax
// on a packed key that encodes (value desc, index asc). The last-finishing
// CTA decodes keys and runs the speculative-accept epilogue.
// ---------------------------------------------------------------------------
__global__ __launch_bounds__(256, 8)
void rejection_sampler_kernel(const float* __restrict__ logits,
                              const unsigned int* __restrict__ spec_words,
                              float* __restrict__ out,
                              int vocab, int rows, int B, int k) {
    const int tid  = threadIdx.x;
    const int step = blockDim.x;
    const int nv4  = vocab >> 2;
    const long long total4 = (long long)rows * (long long)nv4;
    const long long chunk  = (total4 + gridDim.x - 1) / gridDim.x;

    long long s = (long long)blockIdx.x * chunk;
    long long e = s + chunk; if (e > total4) e = total4;

    __shared__ float svals[8];
    __shared__ int   sidx[8];
    __shared__ bool  s_last;

    const float4* __restrict__ p4 = reinterpret_cast<const float4*>(logits);
    const int wid = tid >> 5;
    const int lid = tid & 31;

    while (s < e) {
        const int row = (int)(s / nv4);
        const long long row_start = (long long)row * nv4;
        long long pe = row_start + nv4; if (pe > e) pe = e;

        // ---- per-thread streaming argmax over portion [s, pe) ----
        float best = -FLT_MAX;
        int bidx = 0x7FFFFFFF;
        long long i = s + tid;
        // 8 independent streaming float4 loads per iteration (high MLP).
        for (; i + 7LL * step < pe; i += 8LL * step) {
            #pragma unroll
            for (int j = 0; j < 8; j++) {
                float4 v = __ldcs(&p4[i + (long long)j * step]);
                int base = (int)((i + (long long)j * step - row_start) << 2);
                // Per-thread indices strictly increase -> strict '>' keeps
                // earliest index on ties (jnp.argmax semantics).
                if (v.x > best) { best = v.x; bidx = base; }
                if (v.y > best) { best = v.y; bidx = base + 1; }
                if (v.z > best) { best = v.z; bidx = base + 2; }
                if (v.w > best) { best = v.w; bidx = base + 3; }
            }
        }
        for (; i < pe; i += step) {
            float4 v = __ldcs(&p4[i]);
            int base = (int)((i - row_start) << 2);
            if (v.x > best) { best = v.x; bidx = base; }
            if (v.y > best) { best = v.y; bidx = base + 1; }
            if (v.z > best) { best = v.z; bidx = base + 2; }
            if (v.w > best) { best = v.w; bidx = base + 3; }
        }

        // ---- block reduction (value desc, index asc) ----
        #pragma unroll
        for (int off = 16; off > 0; off >>= 1) {
            float ov = __shfl_down_sync(0xFFFFFFFFu, best, off);
            int   oi = __shfl_down_sync(0xFFFFFFFFu, bidx, off);
            if (ov > best || (ov == best && oi < bidx)) { best = ov; bidx = oi; }
        }
        if (lid == 0) { svals[wid] = best; sidx[wid] = bidx; }
        __syncthreads();
        if (wid == 0) {
            best = (lid < 8) ? svals[lid] : -FLT_MAX;
            bidx = (lid < 8) ? sidx[lid]  : 0x7FFFFFFF;
            #pragma unroll
            for (int off = 4; off > 0; off >>= 1) {
                float ov = __shfl_down_sync(0xFFFFFFFFu, best, off);
                int   oi = __shfl_down_sync(0xFFFFFFFFu, bidx, off);
                if (ov > best || (ov == best && oi < bidx)) { best = ov; bidx = oi; }
            }
            if (lid == 0 && bidx != 0x7FFFFFFF) {
                unsigned long long key =
                    ((unsigned long long)float_ou(best) << 32) |
                    (unsigned long long)(unsigned int)(~bidx);
                atomicMax(&g_key[row], key);
            }
        }
        __syncthreads();   // protect smem reuse on next portion
        s = pe;
    }

    // ---- completion counter ----
    if (tid == 0) {
        __threadfence();
        unsigned int prev = atomicAdd(&g_done, 1u);
        s_last = (prev == gridDim.x - 1u);
    }
    __syncthreads();
    if (!s_last) return;
    __threadfence();   // acquire: make all CTAs' key updates visible

    // ---- decode per-row argmax (plus scalar tail if vocab % 4 != 0) ----
    const int rem = vocab & 3;
    for (int r = tid; r < rows; r += step) {
        unsigned long long key = g_key[r];
        int idx = ~(int)(unsigned int)(key & 0xFFFFFFFFull);
        if (rem) {
            float val = ou_float((unsigned int)(key >> 32));
            const float* rowp = logits + (size_t)r * vocab;
            for (int c = nv4 << 2; c < vocab; c++) {
                float v = rowp[c];
                if (v > val) { val = v; idx = c; }
            }
        }
        g_argmax[r] = idx;
    }
    __syncthreads();

    // ---- speculative-accept logic ----
    if (tid < B) {
        const int b = tid;
        // spec dtype detection: tokens < 2^17 -> int words < 0x20000;
        // float32 patterns (>=1.0) are >= 0x3F800000; int64 -> odd words zero.
        int big = 0, odd_nonzero = 0;
        #pragma unroll
        for (int w = 0; w < 32; w++) {
            unsigned int x = spec_words[w];
            if (x >= 0x01000000u) big++;
            if ((w & 1) && x != 0u) odd_nonzero++;
        }
        int mode = (big > 0) ? 2 : (odd_nonzero == 0 ? 1 : 0); // 2=f32,1=i64,0=i32

        const int kp1 = k + 1;
        int n_acc = 0;
        bool acc = true;
        for (int j = 0; j < k; j++) {
            long long sv;
            if (mode == 2) {
                float f = reinterpret_cast<const float*>(spec_words)[(size_t)b * k + j];
                sv = (long long)f;
            } else if (mode == 1) {
                sv = reinterpret_cast<const long long*>(spec_words)[(size_t)b * k + j];
            } else {
                sv = (long long)reinterpret_cast<const int*>(spec_words)[(size_t)b * k + j];
            }
            int o = g_argmax[b * kp1 + j];
            if (acc && (long long)o == sv) n_acc++; else acc = false;
        }
        for (int j = 0; j < kp1; j++) {
            out[b * kp1 + j] = (j <= n_acc) ? (float)g_argmax[b * kp1 + j] : -1.0f;
        }
    }
    __syncthreads();

    // ---- reset scratch for the next graph replay (only this CTA is alive) ----
    for (int r = tid; r < rows; r += step) g_key[r] = 0ull;
    if (tid == 0) g_done = 0;
}

extern "C" void kernel_launch(void* const* d_in, const int* in_sizes, int n_in,
                              void* d_out, int out_size) {
    const float* logits = (const float*)d_in[0];
    const unsigned int* spec = (const unsigned int*)d_in[1];

    const int rows  = out_size;          // B*(k+1)
    const int nspec = in_sizes[1];       // B*k
    const int B     = rows - nspec;
    const int k     = nspec / B;
    const int vocab = (int)((long long)in_sizes[0] / rows);

    int sms = 148;
    cudaDeviceGetAttribute(&sms, cudaDevAttrMultiProcessorCount, 0);
    int grid = sms * 8;                  // exactly one full wave at occupancy 8

    rejection_sampler_kernel<<<grid, 256>>>(logits, spec, (float*)d_out,
                                            vocab, rows, B, k);
}

// round 5
// speedup vs baseline: 1.0495x; 1.0432x over previous
#include <cuda_runtime.h>
#include <cuda_bf16.h>
#include <float.h>

// Scratch (allocation-free rule: __device__ globals).
__device__ int g_argmax[4096];
__device__ unsigned int g_ticket = 0;   // row work queue
__device__ unsigned int g_done   = 0;   // CTA completion counter
// Both reset by the last CTA for graph-replay determinism.

#define NS       5            // pipeline stages
#define TILE_F4  1280         // float4 per tile -> 20480 bytes
#define TILE_B   (TILE_F4 * 16)
#define THREADS  256

__device__ __forceinline__ unsigned int smem_u32(const void* p) {
    return (unsigned int)__cvta_generic_to_shared(p);
}
__device__ __forceinline__ void mbar_init(unsigned int mbar, unsigned int count) {
    asm volatile("mbarrier.init.shared.b64 [%0], %1;" :: "r"(mbar), "r"(count) : "memory");
}
__device__ __forceinline__ void mbar_expect_tx(unsigned int mbar, unsigned int bytes) {
    asm volatile("mbarrier.arrive.expect_tx.shared.b64 _, [%0], %1;"
                 :: "r"(mbar), "r"(bytes) : "memory");
}
__device__ __forceinline__ void mbar_arrive(unsigned int mbar) {
    asm volatile("mbarrier.arrive.shared.b64 _, [%0];" :: "r"(mbar) : "memory");
}
__device__ __forceinline__ void mbar_wait(unsigned int mbar, unsigned int parity) {
    asm volatile(
        "{\n\t.reg .pred P;\n\t"
        "WAIT_%=:\n\t"
        "mbarrier.try_wait.parity.acquire.cta.shared::cta.b64 P, [%0], %1, 0x989680;\n\t"
        "@P bra.uni DONE_%=;\n\t"
        "bra.uni WAIT_%=;\n\t"
        "DONE_%=:\n\t}"
        :: "r"(mbar), "r"(parity) : "memory");
}
__device__ __forceinline__ void mbar_wait_relaxed(unsigned int mbar, unsigned int parity) {
    asm volatile(
        "{\n\t.reg .pred P;\n\t"
        "WAIT_%=:\n\t"
        "mbarrier.try_wait.parity.relaxed.cta.shared::cta.b64 P, [%0], %1, 0x989680;\n\t"
        "@P bra.uni DONE_%=;\n\t"
        "bra.uni WAIT_%=;\n\t"
        "DONE_%=:\n\t}"
        :: "r"(mbar), "r"(parity) : "memory");
}
__device__ __forceinline__ void bulk_copy_g2s(unsigned int dst_smem, const void* src,
                                              unsigned int bytes, unsigned int mbar) {
    asm volatile(
        "cp.async.bulk.shared::cluster.global.mbarrier::complete_tx::bytes "
        "[%0], [%1], %2, [%3];"
        :: "r"(dst_smem), "l"(src), "r"(bytes), "r"(mbar) : "memory");
}

// ---------------------------------------------------------------------------
// Persistent fused kernel: dynamic row queue; per-row TMA-bulk pipelined
// streaming argmax from SMEM; last-CTA accept epilogue.
// ---------------------------------------------------------------------------
__global__ __launch_bounds__(THREADS, 2)
void rejection_sampler_kernel(const float* __restrict__ logits,
                              const unsigned int* __restrict__ spec_words,
                              float* __restrict__ out,
                              int vocab, int rows, int B, int k) {
    extern __shared__ float4 smem[];                // NS * TILE_F4 float4
    float4* tiles = smem;
    // barriers after the tile buffers: [full0..fullNS-1][empty0..emptyNS-1]
    unsigned long long* bar64 =
        reinterpret_cast<unsigned long long*>(smem + NS * TILE_F4);
    const unsigned int bar_base = smem_u32(bar64);
    #define FULL_BAR(s)  (bar_base + 8u * (unsigned)(s))
    #define EMPTY_BAR(s) (bar_base + 8u * (unsigned)(NS + (s)))

    const int tid = threadIdx.x;
    const int wid = tid >> 5;
    const int lid = tid & 31;
    const int nv4 = vocab >> 2;
    const int tiles_per_row = (nv4 + TILE_F4 - 1) / TILE_F4;
    const int P = (tiles_per_row < NS - 1) ? tiles_per_row : (NS - 1);

    __shared__ float svals[8];
    __shared__ int   sidx[8];
    __shared__ int   s_row;
    __shared__ bool  s_last;

    if (tid == 0) {
        #pragma unroll
        for (int s = 0; s < NS; s++) {
            mbar_init(FULL_BAR(s), 1);        // completes via expect_tx bytes
            mbar_init(EMPTY_BAR(s), THREADS); // all threads arrive after consume
        }
        asm volatile("fence.proxy.async.shared::cta;" ::: "memory");
    }
    __syncthreads();

    long long g = 0;   // global tile cursor for this CTA (drives stage/parity)

    while (true) {
        if (tid == 0) s_row = (int)atomicAdd(&g_ticket, 1u);
        __syncthreads();
        const int row = s_row;
        __syncthreads();
        if (row >= rows) break;

        const float* rowp = logits + (size_t)row * (size_t)vocab;

        // ---- prologue: issue first P copies ----
        if (tid == 0) {
            for (int p = 0; p < P; p++) {
                long long gg = g + p;
                int s = (int)(gg % NS);
                long long i = gg / NS;
                if (i >= 1) mbar_wait_relaxed(EMPTY_BAR(s), (unsigned)((i - 1) & 1));
                int f4off = p * TILE_F4;
                unsigned int bytes = (unsigned int)
                    (((nv4 - f4off) < TILE_F4 ? (nv4 - f4off) : TILE_F4) * 16);
                mbar_expect_tx(FULL_BAR(s), bytes);
                bulk_copy_g2s(smem_u32(tiles + (size_t)s * TILE_F4),
                              rowp + (size_t)f4off * 4, bytes, FULL_BAR(s));
            }
        }

        // ---- steady state ----
        float best = -FLT_MAX;
        int bidx = 0x7FFFFFFF;

        for (int t = 0; t < tiles_per_row; t++, g++) {
            const int s = (int)(g % NS);
            const long long i = g / NS;
            mbar_wait(FULL_BAR(s), (unsigned)(i & 1));

            const int f4base = t * TILE_F4;
            const int n = (nv4 - f4base) < TILE_F4 ? (nv4 - f4base) : TILE_F4;
            const float4* tp = tiles + (size_t)s * TILE_F4;
            for (int j = tid; j < n; j += THREADS) {
                float4 v = tp[j];
                int base = (f4base + j) << 2;
                // Per-thread indices strictly increase within a row, so strict
                // '>' keeps the earliest index on ties (jnp.argmax semantics).
                if (v.x > best) { best = v.x; bidx = base; }
                if (v.y > best) { best = v.y; bidx = base + 1; }
                if (v.z > best) { best = v.z; bidx = base + 2; }
                if (v.w > best) { best = v.w; bidx = base + 3; }
            }
            mbar_arrive(EMPTY_BAR(s));

            // issue copy for tile t+P of this row
            if (tid == 0 && t + P < tiles_per_row) {
                long long gg = g + P;
                int ss = (int)(gg % NS);
                long long ii = gg / NS;
                if (ii >= 1) mbar_wait_relaxed(EMPTY_BAR(ss), (unsigned)((ii - 1) & 1));
                int f4off = (t + P) * TILE_F4;
                unsigned int bytes = (unsigned int)
                    (((nv4 - f4off) < TILE_F4 ? (nv4 - f4off) : TILE_F4) * 16);
                mbar_expect_tx(FULL_BAR(ss), bytes);
                bulk_copy_g2s(smem_u32(tiles + (size_t)ss * TILE_F4),
                              rowp + (size_t)f4off * 4, bytes, FULL_BAR(ss));
            }
        }

        // scalar tail (vocab % 4) via direct loads — tail indices are largest.
        for (int c = (nv4 << 2) + tid; c < vocab; c += THREADS) {
            float v = rowp[c];
            if (v > best) { best = v; bidx = c; }
        }

        // ---- block reduction (value desc, index asc) ----
        #pragma unroll
        for (int off = 16; off > 0; off >>= 1) {
            float ov = __shfl_down_sync(0xFFFFFFFFu, best, off);
            int   oi = __shfl_down_sync(0xFFFFFFFFu, bidx, off);
            if (ov > best || (ov == best && oi < bidx)) { best = ov; bidx = oi; }
        }
        if (lid == 0) { svals[wid] = best; sidx[wid] = bidx; }
        __syncthreads();
        if (wid == 0) {
            best = (lid < 8) ? svals[lid] : -FLT_MAX;
            bidx = (lid < 8) ? sidx[lid]  : 0x7FFFFFFF;
            #pragma unroll
            for (int off = 4; off > 0; off >>= 1) {
                float ov = __shfl_down_sync(0xFFFFFFFFu, best, off);
                int   oi = __shfl_down_sync(0xFFFFFFFFu, bidx, off);
                if (ov > best || (ov == best && oi < bidx)) { best = ov; bidx = oi; }
            }
            if (lid == 0) g_argmax[row] = bidx;
        }
        __syncthreads();
    }

    // ---- completion counter ----
    if (tid == 0) {
        __threadfence();
        unsigned int prev = atomicAdd(&g_done, 1u);
        s_last = (prev == gridDim.x - 1u);
    }
    __syncthreads();
    if (!s_last) return;
    __threadfence();   // acquire all CTAs' g_argmax writes

    // ---- speculative-accept epilogue ----
    if (tid < B) {
        const int b = tid;
        // spec dtype detection: tokens < 2^17 -> int words < 0x20000;
        // float32 (>=1.0) patterns >= 0x3F800000; int64 -> odd words zero.
        int big = 0, odd_nonzero = 0;
        #pragma unroll
        for (int w = 0; w < 32; w++) {
            unsigned int x = spec_words[w];
            if (x >= 0x01000000u) big++;
            if ((w & 1) && x != 0u) odd_nonzero++;
        }
        int mode = (big > 0) ? 2 : (odd_nonzero == 0 ? 1 : 0); // 2=f32,1=i64,0=i32

        const int kp1 = k + 1;
        int n_acc = 0;
        bool acc = true;
        for (int j = 0; j < k; j++) {
            long long sv;
            if (mode == 2) {
                float f = reinterpret_cast<const float*>(spec_words)[(size_t)b * k + j];
                sv = (long long)f;
            } else if (mode == 1) {
                sv = reinterpret_cast<const long long*>(spec_words)[(size_t)b * k + j];
            } else {
                sv = (long long)reinterpret_cast<const int*>(spec_words)[(size_t)b * k + j];
            }
            int o = g_argmax[b * kp1 + j];
            if (acc && (long long)o == sv) n_acc++; else acc = false;
        }
        for (int j = 0; j < kp1; j++) {
            out[b * kp1 + j] = (j <= n_acc) ? (float)g_argmax[b * kp1 + j] : -1.0f;
        }
    }
    __syncthreads();
    if (tid == 0) { g_ticket = 0; g_done = 0; }
}

extern "C" void kernel_launch(void* const* d_in, const int* in_sizes, int n_in,
                              void* d_out, int out_size) {
    const float* logits = (const float*)d_in[0];
    const unsigned int* spec = (const unsigned int*)d_in[1];

    const int rows  = out_size;          // B*(k+1)
    const int nspec = in_sizes[1];       // B*k
    const int B     = rows - nspec;
    const int k     = nspec / B;
    const int vocab = (int)((long long)in_sizes[0] / rows);

    int sms = 148;
    cudaDeviceGetAttribute(&sms, cudaDevAttrMultiProcessorCount, 0);
    const int grid = sms * 2;            // persistent, occupancy-2 (100KB smem)

    const int smem_bytes = NS * TILE_B + 2 * NS * 8 + 16;
    static int configured = 0;
    if (!configured) {
        cudaFuncSetAttribute(rejection_sampler_kernel,
                             cudaFuncAttributeMaxDynamicSharedMemorySize, smem_bytes);
        configured = 1;
    }

    rejection_sampler_kernel<<<grid, THREADS, smem_bytes>>>(
        logits, spec, (float*)d_out, vocab, rows, B, k);
}

// round 6
// speedup vs baseline: 1.0562x; 1.0063x over previous
#include <cuda_runtime.h>
#include <cuda_bf16.h>
#include <float.h>

// Scratch (allocation-free rule: __device__ globals; g_key zero at load and
// re-zeroed by the epilogue CTA for graph-replay determinism).
__device__ unsigned long long g_key[4096];   // per-row packed (ordered_val, ~idx)
__device__ int g_argmax[4096];
__device__ unsigned int g_done = 0;

#define NS       5            // pipeline stages
#define TILE_F4  1280         // float4 per tile -> 20480 bytes
#define TILE_B   (TILE_F4 * 16)
#define THREADS  256

__device__ __forceinline__ unsigned int float_ou(float x) {
    unsigned int u = __float_as_uint(x);
    return (u & 0x80000000u) ? ~u : (u | 0x80000000u);
}
__device__ __forceinline__ float ou_float(unsigned int ou) {
    unsigned int u = (ou & 0x80000000u) ? (ou ^ 0x80000000u) : ~ou;
    return __uint_as_float(u);
}
__device__ __forceinline__ unsigned int smem_u32(const void* p) {
    return (unsigned int)__cvta_generic_to_shared(p);
}
__device__ __forceinline__ void mbar_init(unsigned int mbar, unsigned int count) {
    asm volatile("mbarrier.init.shared.b64 [%0], %1;" :: "r"(mbar), "r"(count) : "memory");
}
__device__ __forceinline__ void mbar_expect_tx(unsigned int mbar, unsigned int bytes) {
    asm volatile("mbarrier.arrive.expect_tx.shared.b64 _, [%0], %1;"
                 :: "r"(mbar), "r"(bytes) : "memory");
}
__device__ __forceinline__ void mbar_arrive(unsigned int mbar) {
    asm volatile("mbarrier.arrive.shared.b64 _, [%0];" :: "r"(mbar) : "memory");
}
__device__ __forceinline__ void mbar_wait(unsigned int mbar, unsigned int parity) {
    asm volatile(
        "{\n\t.reg .pred P;\n\t"
        "WAIT_%=:\n\t"
        "mbarrier.try_wait.parity.acquire.cta.shared::cta.b64 P, [%0], %1, 0x989680;\n\t"
        "@P bra.uni DONE_%=;\n\t"
        "bra.uni WAIT_%=;\n\t"
        "DONE_%=:\n\t}"
        :: "r"(mbar), "r"(parity) : "memory");
}
__device__ __forceinline__ void mbar_wait_relaxed(unsigned int mbar, unsigned int parity) {
    asm volatile(
        "{\n\t.reg .pred P;\n\t"
        "WAIT_%=:\n\t"
        "mbarrier.try_wait.parity.relaxed.cta.shared::cta.b64 P, [%0], %1, 0x989680;\n\t"
        "@P bra.uni DONE_%=;\n\t"
        "bra.uni WAIT_%=;\n\t"
        "DONE_%=:\n\t}"
        :: "r"(mbar), "r"(parity) : "memory");
}
__device__ __forceinline__ void bulk_copy_g2s(unsigned int dst_smem, const void* src,
                                              unsigned int bytes, unsigned int mbar) {
    asm volatile(
        "cp.async.bulk.shared::cluster.global.mbarrier::complete_tx::bytes "
        "[%0], [%1], %2, [%3];"
        :: "r"(dst_smem), "l"(src), "r"(bytes), "r"(mbar) : "memory");
}

// ---------------------------------------------------------------------------
// Continuous-pipeline fused kernel. Global tile index space: rows x
// tiles_per_row (tiles never span rows). Each CTA owns a static contiguous
// tile range and streams it through ONE uninterrupted NS-deep TMA-bulk
// pipeline. Row boundaries only flush the running argmax into g_key[row]
// (packed atomicMax). Last-finishing CTA decodes keys + runs accept logic.
// ---------------------------------------------------------------------------
__global__ __launch_bounds__(THREADS, 2)
void rejection_sampler_kernel(const float* __restrict__ logits,
                              const unsigned int* __restrict__ spec_words,
                              float* __restrict__ out,
                              int vocab, int rows, int B, int k) {
    extern __shared__ float4 smem[];
    float4* tiles = smem;
    unsigned long long* bar64 =
        reinterpret_cast<unsigned long long*>(smem + NS * TILE_F4);
    const unsigned int bar_base = smem_u32(bar64);
    #define FULL_BAR(s)  (bar_base + 8u * (unsigned)(s))
    #define EMPTY_BAR(s) (bar_base + 8u * (unsigned)(NS + (s)))

    const int tid = threadIdx.x;
    const int wid = tid >> 5;
    const int lid = tid & 31;
    const int nv4 = vocab >> 2;
    const int tpr = nv4 / TILE_F4;             // full tiles per row
    const int rem_f4 = nv4 - tpr * TILE_F4;    // leftover float4 per row (last partial tile)
    const int tpr_all = tpr + (rem_f4 ? 1 : 0);
    const long long total_tiles = (long long)rows * tpr_all;
    const long long per_cta = (total_tiles + gridDim.x - 1) / gridDim.x;
    long long t0 = (long long)blockIdx.x * per_cta;
    long long t1 = t0 + per_cta; if (t1 > total_tiles) t1 = total_tiles;
    const long long ntiles = t1 - t0;

    __shared__ float svals[8];
    __shared__ int   sidx[8];
    __shared__ bool  s_last;

    if (tid == 0) {
        #pragma unroll
        for (int s = 0; s < NS; s++) {
            mbar_init(FULL_BAR(s), 1);
            mbar_init(EMPTY_BAR(s), THREADS);
        }
        asm volatile("fence.proxy.async.shared::cta;" ::: "memory");
    }
    __syncthreads();

    if (ntiles > 0) {
        const int P = (int)((ntiles < (long long)(NS - 1)) ? ntiles : (NS - 1));

        // helper lambdas (compiled inline)
        auto tile_src_bytes = [&](long long gt, const float** src, unsigned int* bytes) {
            int row  = (int)(gt / tpr_all);
            int ti   = (int)(gt % tpr_all);
            int f4off = ti * TILE_F4;
            int n = (ti < tpr) ? TILE_F4 : rem_f4;
            *src = logits + (size_t)row * vocab + (size_t)f4off * 4;
            *bytes = (unsigned int)(n * 16);
        };

        // ---- prologue: fill pipeline ----
        if (tid == 0) {
            for (int p = 0; p < P; p++) {
                const float* src; unsigned int bytes;
                tile_src_bytes(t0 + p, &src, &bytes);
                int s = p;   // stages 0..P-1, phase 0
                mbar_expect_tx(FULL_BAR(s), bytes);
                bulk_copy_g2s(smem_u32(tiles + (size_t)s * TILE_F4), src, bytes, FULL_BAR(s));
            }
        }

        float best = -FLT_MAX;
        int bidx = 0x7FFFFFFF;
        int cur_row = (int)(t0 / tpr_all);

        for (long long g = 0; g < ntiles; g++) {
            const long long gt = t0 + g;
            const int row = (int)(gt / tpr_all);
            const int ti  = (int)(gt % tpr_all);

            // ---- row-boundary flush (no pipeline interaction) ----
            if (row != cur_row) {
                #pragma unroll
                for (int off = 16; off > 0; off >>= 1) {
                    float ov = __shfl_down_sync(0xFFFFFFFFu, best, off);
                    int   oi = __shfl_down_sync(0xFFFFFFFFu, bidx, off);
                    if (ov > best || (ov == best && oi < bidx)) { best = ov; bidx = oi; }
                }
                if (lid == 0) { svals[wid] = best; sidx[wid] = bidx; }
                __syncthreads();
                if (wid == 0) {
                    float bv = (lid < 8) ? svals[lid] : -FLT_MAX;
                    int   bi = (lid < 8) ? sidx[lid]  : 0x7FFFFFFF;
                    #pragma unroll
                    for (int off = 4; off > 0; off >>= 1) {
                        float ov = __shfl_down_sync(0xFFFFFFFFu, bv, off);
                        int   oi = __shfl_down_sync(0xFFFFFFFFu, bi, off);
                        if (ov > bv || (ov == bv && oi < bi)) { bv = ov; bi = oi; }
                    }
                    if (lid == 0 && bi != 0x7FFFFFFF) {
                        unsigned long long key =
                            ((unsigned long long)float_ou(bv) << 32) |
                            (unsigned long long)(unsigned int)(~bi);
                        atomicMax(&g_key[cur_row], key);
                    }
                }
                __syncthreads();
                best = -FLT_MAX; bidx = 0x7FFFFFFF;
                cur_row = row;
            }

            // ---- consume tile g ----
            const int s = (int)(g % NS);
            const unsigned int par = (unsigned int)((g / NS) & 1);
            mbar_wait(FULL_BAR(s), par);

            const int f4base = ti * TILE_F4;
            const int n = (ti < tpr) ? TILE_F4 : rem_f4;
            const float4* tp = tiles + (size_t)s * TILE_F4;
            #pragma unroll 5
            for (int j = tid; j < n; j += THREADS) {
                float4 v = tp[j];
                int base = (f4base + j) << 2;
                // Per-thread indices strictly increase within a row portion,
                // so strict '>' keeps earliest index (jnp.argmax semantics).
                if (v.x > best) { best = v.x; bidx = base; }
                if (v.y > best) { best = v.y; bidx = base + 1; }
                if (v.z > best) { best = v.z; bidx = base + 2; }
                if (v.w > best) { best = v.w; bidx = base + 3; }
            }
            mbar_arrive(EMPTY_BAR(s));

            // ---- produce tile g+P (continuous, never drains) ----
            if (tid == 0 && g + P < ntiles) {
                const long long gg = g + P;
                const int ss = (int)(gg % NS);
                const long long ii = gg / NS;
                if (ii >= 1) mbar_wait_relaxed(EMPTY_BAR(ss), (unsigned)((ii - 1) & 1));
                const float* src; unsigned int bytes;
                tile_src_bytes(t0 + gg, &src, &bytes);
                mbar_expect_tx(FULL_BAR(ss), bytes);
                bulk_copy_g2s(smem_u32(tiles + (size_t)ss * TILE_F4), src, bytes, FULL_BAR(ss));
            }
        }

        // ---- final flush for the last row of this CTA's range ----
        #pragma unroll
        for (int off = 16; off > 0; off >>= 1) {
            float ov = __shfl_down_sync(0xFFFFFFFFu, best, off);
            int   oi = __shfl_down_sync(0xFFFFFFFFu, bidx, off);
            if (ov > best || (ov == best && oi < bidx)) { best = ov; bidx = oi; }
        }
        if (lid == 0) { svals[wid] = best; sidx[wid] = bidx; }
        __syncthreads();
        if (wid == 0) {
            float bv = (lid < 8) ? svals[lid] : -FLT_MAX;
            int   bi = (lid < 8) ? sidx[lid]  : 0x7FFFFFFF;
            #pragma unroll
            for (int off = 4; off > 0; off >>= 1) {
                float ov = __shfl_down_sync(0xFFFFFFFFu, bv, off);
                int   oi = __shfl_down_sync(0xFFFFFFFFu, bi, off);
                if (ov > bv || (ov == bv && oi < bi)) { bv = ov; bi = oi; }
            }
            if (lid == 0 && bi != 0x7FFFFFFF) {
                unsigned long long key =
                    ((unsigned long long)float_ou(bv) << 32) |
                    (unsigned long long)(unsigned int)(~bi);
                atomicMax(&g_key[cur_row], key);
            }
        }
    }

    // ---- completion counter ----
    if (tid == 0) {
        __threadfence();
        unsigned int prev = atomicAdd(&g_done, 1u);
        s_last = (prev == gridDim.x - 1u);
    }
    __syncthreads();
    if (!s_last) return;
    __threadfence();   // acquire all CTAs' key updates

    // ---- decode per-row argmax (+ scalar tail if vocab % 4 != 0) ----
    const int remv = vocab & 3;
    for (int r = tid; r < rows; r += THREADS) {
        unsigned long long key = g_key[r];
        int idx = ~(int)(unsigned int)(key & 0xFFFFFFFFull);
        if (remv) {
            float val = ou_float((unsigned int)(key >> 32));
            const float* rowp = logits + (size_t)r * vocab;
            for (int c = nv4 << 2; c < vocab; c++) {
                float v = rowp[c];
                if (v > val) { val = v; idx = c; }
            }
        }
        g_argmax[r] = idx;
    }
    __syncthreads();

    // ---- speculative-accept logic ----
    if (tid < B) {
        const int b = tid;
        // spec dtype detection: tokens < 2^17 -> int words < 0x20000;
        // float32 (>=1.0) patterns >= 0x3F800000; int64 -> odd words zero.
        int big = 0, odd_nonzero = 0;
        #pragma unroll
        for (int w = 0; w < 32; w++) {
            unsigned int x = spec_words[w];
            if (x >= 0x01000000u) big++;
            if ((w & 1) && x != 0u) odd_nonzero++;
        }
        int mode = (big > 0) ? 2 : (odd_nonzero == 0 ? 1 : 0); // 2=f32,1=i64,0=i32

        const int kp1 = k + 1;
        int n_acc = 0;
        bool acc = true;
        for (int j = 0; j < k; j++) {
            long long sv;
            if (mode == 2) {
                float f = reinterpret_cast<const float*>(spec_words)[(size_t)b * k + j];
                sv = (long long)f;
            } else if (mode == 1) {
                sv = reinterpret_cast<const long long*>(spec_words)[(size_t)b * k + j];
            } else {
                sv = (long long)reinterpret_cast<const int*>(spec_words)[(size_t)b * k + j];
            }
            int o = g_argmax[b * kp1 + j];
            if (acc && (long long)o == sv) n_acc++; else acc = false;
        }
        for (int j = 0; j < kp1; j++) {
            out[b * kp1 + j] = (j <= n_acc) ? (float)g_argmax[b * kp1 + j] : -1.0f;
        }
    }
    __syncthreads();
    for (int r = tid; r < rows; r += THREADS) g_key[r] = 0ull;
    if (tid == 0) g_done = 0;
}

extern "C" void kernel_launch(void* const* d_in, const int* in_sizes, int n_in,
                              void* d_out, int out_size) {
    const float* logits = (const float*)d_in[0];
    const unsigned int* spec = (const unsigned int*)d_in[1];

    const int rows  = out_size;          // B*(k+1)
    const int nspec = in_sizes[1];       // B*k
    const int B     = rows - nspec;
    const int k     = nspec / B;
    const int vocab = (int)((long long)in_sizes[0] / rows);

    int sms = 148;
    cudaDeviceGetAttribute(&sms, cudaDevAttrMultiProcessorCount, 0);
    const int grid = sms * 2;            // occupancy-2 (100KB smem each)

    const int smem_bytes = NS * TILE_B + 2 * NS * 8 + 16;
    static int configured = 0;
    if (!configured) {
        cudaFuncSetAttribute(rejection_sampler_kernel,
                             cudaFuncAttributeMaxDynamicSharedMemorySize, smem_bytes);
        configured = 1;
    }

    rejection_sampler_kernel<<<grid, THREADS, smem_bytes>>>(
        logits, spec, (float*)d_out, vocab, rows, B, k);
}